// round 12
// baseline (speedup 1.0000x reference)
#include <cuda_runtime.h>
#include <cuda_bf16.h>
#include <cuda_pipeline.h>
#include <cstdint>

#define NN 100000
#define EE 1600000
#define MPAD 100096     // 782 * 128
#define NBLK 391        // ceil(NN/256)

// ---------------- scratch ----------------
__device__ int   g_counts[NN];
__device__ int   g_bsum[NBLK];
__device__ int   g_boff[NBLK];
__device__ int   g_row[NN + 1];
__device__ int   g_cursor[NN];
__device__ float g_dinv[NN];
__device__ int   g_csrc[EE];

__device__ float g_h[(size_t)MPAD * 128];   // GEMM out (agg input)
__device__ float g_hb[(size_t)MPAD * 128];  // agg out (next GEMM input); rows >= NN stay 0 forever
__device__ float g_c16[(size_t)MPAD * 16];
__device__ __nv_bfloat16 g_w1p[512 * 128];  // [W1h ; W1l]
__device__ __nv_bfloat16 g_w2p[256 * 128];  // [W2h ; W2l]

// ---------------- helpers ----------------
__device__ __forceinline__ uint32_t smem_to_u32(const void* p) {
    uint32_t a;
    asm("{ .reg .u64 t; cvta.to.shared.u64 t, %1; cvt.u32.u64 %0, t; }" : "=r"(a) : "l"(p));
    return a;
}

__device__ __forceinline__ void split4(float4 v, uint2& hi, uint2& lo) {
    __align__(8) __nv_bfloat16 h[4], l[4];
    float f[4] = {v.x, v.y, v.z, v.w};
#pragma unroll
    for (int i = 0; i < 4; i++) {
        h[i] = __float2bfloat16_rn(f[i]);
        l[i] = __float2bfloat16_rn(f[i] - __bfloat162float(h[i]));
    }
    hi = *(uint2*)h;
    lo = *(uint2*)l;
}

__device__ __forceinline__ void split2(float2 v, uint32_t& h, uint32_t& l) {
    __nv_bfloat16 h0 = __float2bfloat16_rn(v.x), h1 = __float2bfloat16_rn(v.y);
    float r0 = v.x - __bfloat162float(h0), r1 = v.y - __bfloat162float(h1);
    __nv_bfloat16 l0 = __float2bfloat16_rn(r0), l1 = __float2bfloat16_rn(r1);
    h = ((uint32_t)__bfloat16_as_ushort(h1) << 16) | (uint32_t)__bfloat16_as_ushort(h0);
    l = ((uint32_t)__bfloat16_as_ushort(l1) << 16) | (uint32_t)__bfloat16_as_ushort(l0);
}

__device__ __forceinline__ void ldsm_x4_t(uint32_t& r0, uint32_t& r1, uint32_t& r2, uint32_t& r3,
                                          uint32_t addr) {
    asm volatile("ldmatrix.sync.aligned.m8n8.x4.trans.shared.b16 {%0,%1,%2,%3}, [%4];"
                 : "=r"(r0), "=r"(r1), "=r"(r2), "=r"(r3) : "r"(addr));
}

__device__ __forceinline__ void mma_16816(float* c, const uint32_t* a, const uint32_t* b) {
    asm volatile(
        "mma.sync.aligned.m16n8k16.row.col.f32.bf16.bf16.f32 "
        "{%0,%1,%2,%3}, {%4,%5,%6,%7}, {%8,%9}, {%0,%1,%2,%3};"
        : "+f"(c[0]), "+f"(c[1]), "+f"(c[2]), "+f"(c[3])
        : "r"(a[0]), "r"(a[1]), "r"(a[2]), "r"(a[3]), "r"(b[0]), "r"(b[1]));
}

// W[K,128] -> WP[2K,128] = [Wh ; Wl]
__global__ void k_split_w(const float* __restrict__ W, __nv_bfloat16* __restrict__ WP, int K) {
    int i = blockIdx.x * blockDim.x + threadIdx.x;
    if (i >= K * 32) return;
    int row = i >> 5, c4 = (i & 31) * 4;
    float4 v = ((const float4*)W)[i];
    uint2 h, l; split4(v, h, l);
    *(uint2*)(WP + (size_t)row * 128 + c4)       = h;
    *(uint2*)(WP + (size_t)(K + row) * 128 + c4) = l;
}

// ---------------- CSR build ----------------
__global__ void k_zero_counts() {
    int i = blockIdx.x * blockDim.x + threadIdx.x;
    if (i < NN) g_counts[i] = 0;
}

__global__ void k_hist(const int* __restrict__ dst) {
    int i = blockIdx.x * blockDim.x + threadIdx.x;
    if (i < EE / 4) {
        int4 d = ((const int4*)dst)[i];
        atomicAdd(&g_counts[d.x], 1);
        atomicAdd(&g_counts[d.y], 1);
        atomicAdd(&g_counts[d.z], 1);
        atomicAdd(&g_counts[d.w], 1);
    }
}

__global__ void k_scan_part() {
    __shared__ int sm[256];
    int i = blockIdx.x * 256 + threadIdx.x;
    sm[threadIdx.x] = (i < NN) ? g_counts[i] : 0;
    __syncthreads();
#pragma unroll
    for (int off = 128; off > 0; off >>= 1) {
        if (threadIdx.x < off) sm[threadIdx.x] += sm[threadIdx.x + off];
        __syncthreads();
    }
    if (threadIdx.x == 0) g_bsum[blockIdx.x] = sm[0];
}

__global__ void k_scan_top() {
    __shared__ int sm[512];
    int t = threadIdx.x;
    sm[t] = (t < NBLK) ? g_bsum[t] : 0;
    __syncthreads();
    for (int off = 1; off < 512; off <<= 1) {
        int v = (t >= off) ? sm[t - off] : 0;
        __syncthreads();
        sm[t] += v;
        __syncthreads();
    }
    if (t < NBLK) g_boff[t] = (t == 0) ? 0 : sm[t - 1];
}

__global__ void k_scan_write() {
    int b = blockIdx.x, t = threadIdx.x;
    int i = b * 256 + t;
    int c = (i < NN) ? g_counts[i] : 0;
    int lane = t & 31, w = t >> 5;
    int v = c;
#pragma unroll
    for (int off = 1; off < 32; off <<= 1) {
        int u = __shfl_up_sync(0xffffffffu, v, off);
        if (lane >= off) v += u;
    }
    __shared__ int wsum[8];
    if (lane == 31) wsum[w] = v;
    __syncthreads();
    if (w == 0) {
        int x = (lane < 8) ? wsum[lane] : 0;
#pragma unroll
        for (int off = 1; off < 8; off <<= 1) {
            int u = __shfl_up_sync(0xffffffffu, x, off);
            if (lane >= off) x += u;
        }
        if (lane < 8) wsum[lane] = x;
    }
    __syncthreads();
    int excl = v - c + ((w > 0) ? wsum[w - 1] : 0) + g_boff[b];
    if (i < NN) {
        g_row[i]    = excl;
        g_cursor[i] = excl;
        g_dinv[i]   = rsqrtf((float)(c + 1));
    }
    if (i == NN - 1) g_row[NN] = excl + c;
}

__global__ void k_scatter(const int* __restrict__ src, const int* __restrict__ dst) {
    int i = blockIdx.x * blockDim.x + threadIdx.x;
    if (i < EE / 4) {
        int4 s = ((const int4*)src)[i];
        int4 d = ((const int4*)dst)[i];
        int p;
        p = atomicAdd(&g_cursor[d.x], 1); g_csrc[p] = s.x;
        p = atomicAdd(&g_cursor[d.y], 1); g_csrc[p] = s.y;
        p = atomicAdd(&g_cursor[d.z], 1); g_csrc[p] = s.z;
        p = atomicAdd(&g_cursor[d.w], 1); g_csrc[p] = s.w;
    }
}

// ---------------- raw-mma fused-split GEMM: C[.,128] = A_fp32[.,K] * W[K,128] ----------------
// Warp tile 32x64 (wm 0..3, wn 0..1): halves cross-warp ldmatrix duplication vs 16x128.
template <int K>
__global__ __launch_bounds__(256, 2) void fgemm_mma(
    const float* __restrict__ A, const __nv_bfloat16* __restrict__ WP,
    float* __restrict__ C, int M)
{
    constexpr int NCH  = K / 32;
    constexpr int LDBB = 272;
    constexpr int HALF = 32 * LDBB;
    constexpr int STAGE = 2 * HALF;

    __shared__ __align__(16) char sB[2 * STAGE];

    const int tid  = threadIdx.x;
    const int warp = tid >> 5;
    const int lane = tid & 31;
    const int wm   = warp >> 1;          // 0..3 -> 32-row slab
    const int wn   = warp & 1;           // 0..1 -> 64-col slab
    const int m0   = wm * 32;
    const size_t rowBase = (size_t)blockIdx.x * 128;
    const uint32_t sbase = smem_to_u32(sB);

    auto issueB = [&](int ch) {
        int st = ch & 1, k0 = ch * 32;
#pragma unroll
        for (int rep = 0; rep < 4; rep++) {
            int idx  = tid + rep * 256;
            int half = idx >> 9;
            int r    = (idx >> 4) & 31;
            int c16  = idx & 15;
            __pipeline_memcpy_async(
                sB + st * STAGE + half * HALF + r * LDBB + c16 * 16,
                (const char*)WP + ((size_t)(half * K + k0 + r) * 256 + c16 * 16), 16);
        }
    };

    const int rlo  = lane >> 2;
    const int tcol = (lane & 3) * 2;
    float2 p[8], pn[8];   // frag0: p[0..3] (rows m0+rlo, +8); frag1: p[4..7] (rows m0+16+rlo, +24)
    auto ldA = [&](float2* buf, int g) {
        int k = g * 16 + tcol;
        size_t r0 = rowBase + m0 + rlo;
#pragma unroll
        for (int f = 0; f < 2; f++) {
            size_t ra = r0 + f * 16;
            size_t rb = ra + 8;
            buf[f*4+0] = (ra < (size_t)M) ? *(const float2*)&A[ra * K + k]     : make_float2(0.f, 0.f);
            buf[f*4+1] = (rb < (size_t)M) ? *(const float2*)&A[rb * K + k]     : make_float2(0.f, 0.f);
            buf[f*4+2] = (ra < (size_t)M) ? *(const float2*)&A[ra * K + k + 8] : make_float2(0.f, 0.f);
            buf[f*4+3] = (rb < (size_t)M) ? *(const float2*)&A[rb * K + k + 8] : make_float2(0.f, 0.f);
        }
    };

    float c[2][8][4];   // [m-frag][n8][quad]
#pragma unroll
    for (int f = 0; f < 2; f++)
#pragma unroll
        for (int i = 0; i < 8; i++)
#pragma unroll
            for (int j = 0; j < 4; j++) c[f][i][j] = 0.f;

    issueB(0);
    __pipeline_commit();
    ldA(p, 0);

    const int krow  = (lane & 7) + ((lane >> 3) & 1) * 8;
    const int nside = ((lane >> 4) & 1) * 8;

    for (int ch = 0; ch < NCH; ch++) {
        int st = ch & 1;
        __pipeline_wait_prior(0);
        __syncthreads();
        if (ch + 1 < NCH) { issueB(ch + 1); __pipeline_commit(); }

#pragma unroll
        for (int h16 = 0; h16 < 2; h16++) {
            uint32_t ah[2][4], al[2][4];
#pragma unroll
            for (int f = 0; f < 2; f++)
#pragma unroll
                for (int q = 0; q < 4; q++)
                    split2(p[f*4+q], ah[f][q], al[f][q]);
            int g = ch * 2 + h16;
            if (g + 1 < K / 16) ldA(pn, g + 1);

            // B cols for this warp: wn*64 .. wn*64+63 (4 n16 groups)
            uint32_t bh_base = sbase + st * STAGE + (h16 * 16 + krow) * LDBB
                             + (wn * 64 + nside) * 2;
            uint32_t bl_base = bh_base + HALF;
#pragma unroll
            for (int grp = 0; grp < 4; grp++) {
                uint32_t h0, h1, h2, h3, l0, l1, l2, l3;
                ldsm_x4_t(h0, h1, h2, h3, bh_base + grp * 32);
                ldsm_x4_t(l0, l1, l2, l3, bl_base + grp * 32);
                uint32_t bA[2] = {h0, h1}, bB[2] = {h2, h3};
                uint32_t lA[2] = {l0, l1}, lB[2] = {l2, l3};
#pragma unroll
                for (int f = 0; f < 2; f++) {
                    mma_16816(c[f][grp * 2],     ah[f], bA);
                    mma_16816(c[f][grp * 2],     al[f], bA);
                    mma_16816(c[f][grp * 2],     ah[f], lA);
                    mma_16816(c[f][grp * 2 + 1], ah[f], bB);
                    mma_16816(c[f][grp * 2 + 1], al[f], bB);
                    mma_16816(c[f][grp * 2 + 1], ah[f], lB);
                }
            }
#pragma unroll
            for (int q = 0; q < 8; q++) p[q] = pn[q];
        }
    }

    // epilogue: C rows padded to MPAD; unguarded vector stores
#pragma unroll
    for (int f = 0; f < 2; f++) {
        size_t ra = rowBase + m0 + f * 16 + rlo;
#pragma unroll
        for (int n8 = 0; n8 < 8; n8++) {
            int col = wn * 64 + n8 * 8 + tcol;
            *(float2*)&C[ra * 128 + col]       = make_float2(c[f][n8][0], c[f][n8][1]);
            *(float2*)&C[(ra + 8) * 128 + col] = make_float2(c[f][n8][2], c[f][n8][3]);
        }
    }
}

// ---------------- small GEMM: C[M,16] = A[M,128] * W[128,16] ----------------
__global__ __launch_bounds__(256) void gemm16(
    const float* __restrict__ A, const float* __restrict__ W,
    float* __restrict__ C, int M)
{
    __shared__ float xs[64][132];
    __shared__ float ws[128][16];

    int tid = threadIdx.x;
    int r0 = blockIdx.x * 64;

    for (int i = tid; i < 2048; i += 256) {
        int row = i >> 5;
        int c4 = i & 31;
        int gr = r0 + row;
        float4 v = (gr < M) ? *(const float4*)(A + (size_t)gr * 128 + c4 * 4)
                            : make_float4(0.f, 0.f, 0.f, 0.f);
        *(float4*)(&xs[row][c4 * 4]) = v;
    }
    for (int i = tid; i < 2048; i += 256) ws[i >> 4][i & 15] = W[i];
    __syncthreads();

    int col = tid & 15;
    int rq  = tid >> 4;
    float acc[4] = {0.f, 0.f, 0.f, 0.f};
    for (int k = 0; k < 128; k++) {
        float w = ws[k][col];
#pragma unroll
        for (int r = 0; r < 4; r++)
            acc[r] = fmaf(xs[rq * 4 + r][k], w, acc[r]);
    }
#pragma unroll
    for (int r = 0; r < 4; r++) {
        int gr = r0 + rq * 4 + r;
        if (gr < M) C[(size_t)gr * 16 + col] = acc[r];
    }
}

// ---------------- aggregation, F=128 (MLP-8 predicated gather) ----------------
template <bool RELU>
__global__ __launch_bounds__(256) void agg128(
    const float4* __restrict__ h, const float* __restrict__ bias,
    float4* __restrict__ outF)
{
    int warp = (blockIdx.x * blockDim.x + threadIdx.x) >> 5;
    int lane = threadIdx.x & 31;
    if (warp >= NN) return;
    int v = warp;

    float dv = g_dinv[v];
    float4 self = h[(size_t)v * 32 + lane];
    float4 acc;
    acc.x = dv * self.x; acc.y = dv * self.y;
    acc.z = dv * self.z; acc.w = dv * self.w;

    int rs = g_row[v], re = g_row[v + 1];
    for (int base = rs; base < re; base += 32) {
        int avail = re - base;
        int   s = 0;
        float d = 0.f;
        if (lane < avail) { s = g_csrc[base + lane]; d = g_dinv[s]; }
        int m = avail < 32 ? avail : 32;
        for (int j = 0; j < m; j += 8) {
            int   sj[8];
            float dj[8];
#pragma unroll
            for (int q = 0; q < 8; q++) {
                sj[q] = __shfl_sync(0xffffffffu, s, j + q);
                dj[q] = __shfl_sync(0xffffffffu, d, j + q);
            }
            float4 hv[8];
#pragma unroll
            for (int q = 0; q < 8; q++)
                hv[q] = h[(size_t)sj[q] * 32 + lane];
#pragma unroll
            for (int q = 0; q < 8; q++) {
                acc.x = fmaf(dj[q], hv[q].x, acc.x);
                acc.y = fmaf(dj[q], hv[q].y, acc.y);
                acc.z = fmaf(dj[q], hv[q].z, acc.z);
                acc.w = fmaf(dj[q], hv[q].w, acc.w);
            }
        }
    }

    float4 bb = *(const float4*)(bias + 4 * lane);
    acc.x = fmaf(acc.x, dv, bb.x);
    acc.y = fmaf(acc.y, dv, bb.y);
    acc.z = fmaf(acc.z, dv, bb.z);
    acc.w = fmaf(acc.w, dv, bb.w);
    if (RELU) {
        acc.x = fmaxf(acc.x, 0.f); acc.y = fmaxf(acc.y, 0.f);
        acc.z = fmaxf(acc.z, 0.f); acc.w = fmaxf(acc.w, 0.f);
    }
    outF[(size_t)v * 32 + lane] = acc;
}

// ---------------- aggregation, F=16 (MLP-8 predicated gather) ----------------
__global__ __launch_bounds__(256) void agg16(
    const float* __restrict__ h, const float* __restrict__ bias,
    float* __restrict__ out)
{
    int warp = (blockIdx.x * blockDim.x + threadIdx.x) >> 5;
    int lane = threadIdx.x & 31;
    if (warp >= NN) return;
    int v = warp;

    float dv = g_dinv[v];
    float acc = (lane < 16) ? dv * h[(size_t)v * 16 + lane] : 0.f;

    int rs = g_row[v], re = g_row[v + 1];
    for (int base = rs; base < re; base += 32) {
        int avail = re - base;
        int   s = 0;
        float d = 0.f;
        if (lane < avail) { s = g_csrc[base + lane]; d = g_dinv[s]; }
        int m = avail < 32 ? avail : 32;
        for (int j = 0; j < m; j += 8) {
            int   sj[8];
            float dj[8];
#pragma unroll
            for (int q = 0; q < 8; q++) {
                sj[q] = __shfl_sync(0xffffffffu, s, j + q);
                dj[q] = __shfl_sync(0xffffffffu, d, j + q);
            }
            float hv[8];
#pragma unroll
            for (int q = 0; q < 8; q++)
                hv[q] = (lane < 16) ? h[(size_t)sj[q] * 16 + lane] : 0.f;
#pragma unroll
            for (int q = 0; q < 8; q++)
                acc = fmaf(dj[q], hv[q], acc);
        }
    }

    if (lane < 16) {
        acc = fmaf(acc, dv, bias[lane]);
        out[(size_t)v * 16 + lane] = acc;
    }
}

// ---------------- launch ----------------
extern "C" void kernel_launch(void* const* d_in, const int* in_sizes, int n_in,
                              void* d_out, int out_size)
{
    const float* x  = (const float*)d_in[0];
    const int*   ei = (const int*)d_in[1];
    const float* W1 = (const float*)d_in[2];
    const float* b1 = (const float*)d_in[3];
    const float* W2 = (const float*)d_in[4];
    const float* b2 = (const float*)d_in[5];
    const float* W3 = (const float*)d_in[6];
    const float* b3 = (const float*)d_in[7];
    float* out = (float*)d_out;

    float *pH, *pHB, *pC16;
    __nv_bfloat16 *pW1P, *pW2P;
    cudaGetSymbolAddress((void**)&pH,   g_h);
    cudaGetSymbolAddress((void**)&pHB,  g_hb);
    cudaGetSymbolAddress((void**)&pC16, g_c16);
    cudaGetSymbolAddress((void**)&pW1P, g_w1p);
    cudaGetSymbolAddress((void**)&pW2P, g_w2p);

    static cudaStream_t s1 = nullptr;
    static cudaEvent_t  e0 = nullptr, e1 = nullptr;
    if (!s1) {
        cudaStreamCreateWithFlags(&s1, cudaStreamNonBlocking);
        cudaEventCreateWithFlags(&e0, cudaEventDisableTiming);
        cudaEventCreateWithFlags(&e1, cudaEventDisableTiming);
    }

    const int* e_src = ei;
    const int* e_dst = ei + EE;

    const int AGG_BLOCKS  = (NN + 7) / 8;
    const int GEMM_BLOCKS = MPAD / 128;  // 782

    // Fork: CSR chain + W2 split on s1, concurrent with W1 split + fgemm1 on stream 0.
    cudaEventRecord(e0, 0);
    cudaStreamWaitEvent(s1, e0, 0);

    // submissions 1-2 (s1): zero, hist
    k_zero_counts<<<(NN + 255) / 256, 256, 0, s1>>>();
    k_hist<<<(EE / 4 + 255) / 256, 256, 0, s1>>>(e_dst);

    // submissions 3-4 (stream 0): W1 split + fgemm1 (profiled slot = 4th)
    k_split_w<<<(256 * 32 + 255) / 256, 256>>>(W1, pW1P, 256);
    fgemm_mma<256><<<GEMM_BLOCKS, 256>>>(x, pW1P, pH, NN);

    // remainder of CSR chain + W2 split on s1
    k_scan_part<<<NBLK, 256, 0, s1>>>();
    k_scan_top<<<1, 512, 0, s1>>>();
    k_scan_write<<<NBLK, 256, 0, s1>>>();
    k_scatter<<<(EE / 4 + 255) / 256, 256, 0, s1>>>(e_src, e_dst);
    k_split_w<<<(128 * 32 + 255) / 256, 256, 0, s1>>>(W2, pW2P, 128);
    cudaEventRecord(e1, s1);

    cudaStreamWaitEvent(0, e1, 0);   // stream0 now has fgemm1 + CSR done

    // Layer 1 aggregation (h1 -> g_hb)
    agg128<true><<<AGG_BLOCKS, 256>>>((const float4*)pH, b1, (float4*)pHB);

    // Layer 2 GEMM (padded rows of g_hb are zero -> unguarded reads safe)
    fgemm_mma<128><<<GEMM_BLOCKS, 256>>>(pHB, pW2P, pH, MPAD);

    // Layer 2 aggregation
    agg128<true><<<AGG_BLOCKS, 256>>>((const float4*)pH, b2, (float4*)pHB);

    // Layer 3
    gemm16<<<(NN + 63) / 64, 256>>>(pHB, W3, pC16, NN);
    agg16<<<AGG_BLOCKS, 256>>>(pC16, b3, out);
}

// round 13
// speedup vs baseline: 1.0584x; 1.0584x over previous
#include <cuda_runtime.h>
#include <cuda_bf16.h>
#include <cuda_fp16.h>
#include <cuda_pipeline.h>
#include <cstdint>

#define NN 100000
#define EE 1600000
#define MPAD 100096     // 782 * 128
#define NBLK 391        // ceil(NN/256)

// ---------------- scratch ----------------
__device__ int   g_counts[NN];
__device__ int   g_bsum[NBLK];
__device__ int   g_boff[NBLK];
__device__ int   g_row[NN + 1];
__device__ int   g_cursor[NN];
__device__ float g_dinv[NN];
__device__ int   g_csrc[EE];

__device__ __half g_h16[(size_t)MPAD * 128]; // fgemm1 out (fp16, agg1 gather input)
__device__ float g_h[(size_t)MPAD * 128];    // fgemm2 out (fp32, agg2 input)
__device__ float g_hb[(size_t)MPAD * 128];   // agg out (next GEMM input); rows >= NN stay 0
__device__ float g_c16[(size_t)MPAD * 16];
__device__ __nv_bfloat16 g_w1p[512 * 128];   // [W1h ; W1l]
__device__ __nv_bfloat16 g_w2p[256 * 128];   // [W2h ; W2l]

// ---------------- helpers ----------------
__device__ __forceinline__ uint32_t smem_to_u32(const void* p) {
    uint32_t a;
    asm("{ .reg .u64 t; cvta.to.shared.u64 t, %1; cvt.u32.u64 %0, t; }" : "=r"(a) : "l"(p));
    return a;
}

__device__ __forceinline__ void split4(float4 v, uint2& hi, uint2& lo) {
    __align__(8) __nv_bfloat16 h[4], l[4];
    float f[4] = {v.x, v.y, v.z, v.w};
#pragma unroll
    for (int i = 0; i < 4; i++) {
        h[i] = __float2bfloat16_rn(f[i]);
        l[i] = __float2bfloat16_rn(f[i] - __bfloat162float(h[i]));
    }
    hi = *(uint2*)h;
    lo = *(uint2*)l;
}

__device__ __forceinline__ void split2(float2 v, uint32_t& h, uint32_t& l) {
    __nv_bfloat16 h0 = __float2bfloat16_rn(v.x), h1 = __float2bfloat16_rn(v.y);
    float r0 = v.x - __bfloat162float(h0), r1 = v.y - __bfloat162float(h1);
    __nv_bfloat16 l0 = __float2bfloat16_rn(r0), l1 = __float2bfloat16_rn(r1);
    h = ((uint32_t)__bfloat16_as_ushort(h1) << 16) | (uint32_t)__bfloat16_as_ushort(h0);
    l = ((uint32_t)__bfloat16_as_ushort(l1) << 16) | (uint32_t)__bfloat16_as_ushort(l0);
}

__device__ __forceinline__ void ldsm_x4_t(uint32_t& r0, uint32_t& r1, uint32_t& r2, uint32_t& r3,
                                          uint32_t addr) {
    asm volatile("ldmatrix.sync.aligned.m8n8.x4.trans.shared.b16 {%0,%1,%2,%3}, [%4];"
                 : "=r"(r0), "=r"(r1), "=r"(r2), "=r"(r3) : "r"(addr));
}

__device__ __forceinline__ void mma_16816(float* c, const uint32_t* a, const uint32_t* b) {
    asm volatile(
        "mma.sync.aligned.m16n8k16.row.col.f32.bf16.bf16.f32 "
        "{%0,%1,%2,%3}, {%4,%5,%6,%7}, {%8,%9}, {%0,%1,%2,%3};"
        : "+f"(c[0]), "+f"(c[1]), "+f"(c[2]), "+f"(c[3])
        : "r"(a[0]), "r"(a[1]), "r"(a[2]), "r"(a[3]), "r"(b[0]), "r"(b[1]));
}

// W[K,128] -> WP[2K,128] = [Wh ; Wl]
__global__ void k_split_w(const float* __restrict__ W, __nv_bfloat16* __restrict__ WP, int K) {
    int i = blockIdx.x * blockDim.x + threadIdx.x;
    if (i >= K * 32) return;
    int row = i >> 5, c4 = (i & 31) * 4;
    float4 v = ((const float4*)W)[i];
    uint2 h, l; split4(v, h, l);
    *(uint2*)(WP + (size_t)row * 128 + c4)       = h;
    *(uint2*)(WP + (size_t)(K + row) * 128 + c4) = l;
}

// ---------------- CSR build ----------------
__global__ void k_zero_counts() {
    int i = blockIdx.x * blockDim.x + threadIdx.x;
    if (i < NN) g_counts[i] = 0;
}

__global__ void k_hist(const int* __restrict__ dst) {
    int i = blockIdx.x * blockDim.x + threadIdx.x;
    if (i < EE / 4) {
        int4 d = ((const int4*)dst)[i];
        atomicAdd(&g_counts[d.x], 1);
        atomicAdd(&g_counts[d.y], 1);
        atomicAdd(&g_counts[d.z], 1);
        atomicAdd(&g_counts[d.w], 1);
    }
}

__global__ void k_scan_part() {
    __shared__ int sm[256];
    int i = blockIdx.x * 256 + threadIdx.x;
    sm[threadIdx.x] = (i < NN) ? g_counts[i] : 0;
    __syncthreads();
#pragma unroll
    for (int off = 128; off > 0; off >>= 1) {
        if (threadIdx.x < off) sm[threadIdx.x] += sm[threadIdx.x + off];
        __syncthreads();
    }
    if (threadIdx.x == 0) g_bsum[blockIdx.x] = sm[0];
}

__global__ void k_scan_top() {
    __shared__ int sm[512];
    int t = threadIdx.x;
    sm[t] = (t < NBLK) ? g_bsum[t] : 0;
    __syncthreads();
    for (int off = 1; off < 512; off <<= 1) {
        int v = (t >= off) ? sm[t - off] : 0;
        __syncthreads();
        sm[t] += v;
        __syncthreads();
    }
    if (t < NBLK) g_boff[t] = (t == 0) ? 0 : sm[t - 1];
}

__global__ void k_scan_write() {
    int b = blockIdx.x, t = threadIdx.x;
    int i = b * 256 + t;
    int c = (i < NN) ? g_counts[i] : 0;
    int lane = t & 31, w = t >> 5;
    int v = c;
#pragma unroll
    for (int off = 1; off < 32; off <<= 1) {
        int u = __shfl_up_sync(0xffffffffu, v, off);
        if (lane >= off) v += u;
    }
    __shared__ int wsum[8];
    if (lane == 31) wsum[w] = v;
    __syncthreads();
    if (w == 0) {
        int x = (lane < 8) ? wsum[lane] : 0;
#pragma unroll
        for (int off = 1; off < 8; off <<= 1) {
            int u = __shfl_up_sync(0xffffffffu, x, off);
            if (lane >= off) x += u;
        }
        if (lane < 8) wsum[lane] = x;
    }
    __syncthreads();
    int excl = v - c + ((w > 0) ? wsum[w - 1] : 0) + g_boff[b];
    if (i < NN) {
        g_row[i]    = excl;
        g_cursor[i] = excl;
        g_dinv[i]   = rsqrtf((float)(c + 1));
    }
    if (i == NN - 1) g_row[NN] = excl + c;
}

__global__ void k_scatter(const int* __restrict__ src, const int* __restrict__ dst) {
    int i = blockIdx.x * blockDim.x + threadIdx.x;
    if (i < EE / 4) {
        int4 s = ((const int4*)src)[i];
        int4 d = ((const int4*)dst)[i];
        int p;
        p = atomicAdd(&g_cursor[d.x], 1); g_csrc[p] = s.x;
        p = atomicAdd(&g_cursor[d.y], 1); g_csrc[p] = s.y;
        p = atomicAdd(&g_cursor[d.z], 1); g_csrc[p] = s.z;
        p = atomicAdd(&g_cursor[d.w], 1); g_csrc[p] = s.w;
    }
}

// ---------------- raw-mma fused-split GEMM (round-11 shape): C = A_fp32 * W ----------------
// Warp tile 16x128. OUT_HALF: write C as fp16 (for the fp16 gather path).
template <int K, bool OUT_HALF>
__global__ __launch_bounds__(256, 2) void fgemm_mma(
    const float* __restrict__ A, const __nv_bfloat16* __restrict__ WP,
    void* __restrict__ Cv, int M)
{
    constexpr int NCH  = K / 32;
    constexpr int LDBB = 272;
    constexpr int HALF = 32 * LDBB;
    constexpr int STAGE = 2 * HALF;

    __shared__ __align__(16) char sB[2 * STAGE];

    const int tid  = threadIdx.x;
    const int warp = tid >> 5;
    const int lane = tid & 31;
    const int m0   = warp * 16;
    const size_t rowBase = (size_t)blockIdx.x * 128;
    const uint32_t sbase = smem_to_u32(sB);

    auto issueB = [&](int ch) {
        int st = ch & 1, k0 = ch * 32;
#pragma unroll
        for (int rep = 0; rep < 4; rep++) {
            int idx  = tid + rep * 256;
            int half = idx >> 9;
            int r    = (idx >> 4) & 31;
            int c16  = idx & 15;
            __pipeline_memcpy_async(
                sB + st * STAGE + half * HALF + r * LDBB + c16 * 16,
                (const char*)WP + ((size_t)(half * K + k0 + r) * 256 + c16 * 16), 16);
        }
    };

    const int rlo  = lane >> 2;
    const int tcol = (lane & 3) * 2;
    float2 p0, p1, p2, p3;
    auto ldA = [&](int g) {
        int k = g * 16 + tcol;
        size_t ra = rowBase + m0 + rlo;
        size_t rb = ra + 8;
        p0 = (ra < (size_t)M) ? *(const float2*)&A[ra * K + k]     : make_float2(0.f, 0.f);
        p1 = (rb < (size_t)M) ? *(const float2*)&A[rb * K + k]     : make_float2(0.f, 0.f);
        p2 = (ra < (size_t)M) ? *(const float2*)&A[ra * K + k + 8] : make_float2(0.f, 0.f);
        p3 = (rb < (size_t)M) ? *(const float2*)&A[rb * K + k + 8] : make_float2(0.f, 0.f);
    };

    float c[16][4];
#pragma unroll
    for (int i = 0; i < 16; i++)
#pragma unroll
        for (int j = 0; j < 4; j++) c[i][j] = 0.f;

    issueB(0);
    __pipeline_commit();
    ldA(0);

    const int krow  = (lane & 7) + ((lane >> 3) & 1) * 8;
    const int nside = ((lane >> 4) & 1) * 8;

    for (int ch = 0; ch < NCH; ch++) {
        int st = ch & 1;
        __pipeline_wait_prior(0);
        __syncthreads();
        if (ch + 1 < NCH) { issueB(ch + 1); __pipeline_commit(); }

#pragma unroll
        for (int h16 = 0; h16 < 2; h16++) {
            uint32_t ah[4], al[4];
            split2(p0, ah[0], al[0]);
            split2(p1, ah[1], al[1]);
            split2(p2, ah[2], al[2]);
            split2(p3, ah[3], al[3]);
            int g = ch * 2 + h16;
            if (g + 1 < K / 16) ldA(g + 1);

            uint32_t bh_base = sbase + st * STAGE + (h16 * 16 + krow) * LDBB + nside * 2;
            uint32_t bl_base = bh_base + HALF;
#pragma unroll
            for (int grp = 0; grp < 8; grp++) {
                uint32_t h0, h1, h2, h3, l0, l1, l2, l3;
                ldsm_x4_t(h0, h1, h2, h3, bh_base + grp * 32);
                ldsm_x4_t(l0, l1, l2, l3, bl_base + grp * 32);
                uint32_t bA[2] = {h0, h1}, bB[2] = {h2, h3};
                uint32_t lA[2] = {l0, l1}, lB[2] = {l2, l3};
                mma_16816(c[grp * 2],     ah, bA);
                mma_16816(c[grp * 2],     al, bA);
                mma_16816(c[grp * 2],     ah, lA);
                mma_16816(c[grp * 2 + 1], ah, bB);
                mma_16816(c[grp * 2 + 1], al, bB);
                mma_16816(c[grp * 2 + 1], ah, lB);
            }
        }
    }

    size_t ra = rowBase + m0 + rlo;
    if (OUT_HALF) {
        __half2* Ch = (__half2*)Cv;
#pragma unroll
        for (int n8 = 0; n8 < 16; n8++) {
            int col = n8 * 8 + tcol;       // even
            Ch[(ra * 128 + col) >> 1]       = __floats2half2_rn(c[n8][0], c[n8][1]);
            Ch[((ra + 8) * 128 + col) >> 1] = __floats2half2_rn(c[n8][2], c[n8][3]);
        }
    } else {
        float* C = (float*)Cv;
#pragma unroll
        for (int n8 = 0; n8 < 16; n8++) {
            int col = n8 * 8 + tcol;
            *(float2*)&C[ra * 128 + col]       = make_float2(c[n8][0], c[n8][1]);
            *(float2*)&C[(ra + 8) * 128 + col] = make_float2(c[n8][2], c[n8][3]);
        }
    }
}

// ---------------- small GEMM: C[M,16] = A[M,128] * W[128,16] ----------------
__global__ __launch_bounds__(256) void gemm16(
    const float* __restrict__ A, const float* __restrict__ W,
    float* __restrict__ C, int M)
{
    __shared__ float xs[64][132];
    __shared__ float ws[128][16];

    int tid = threadIdx.x;
    int r0 = blockIdx.x * 64;

    for (int i = tid; i < 2048; i += 256) {
        int row = i >> 5;
        int c4 = i & 31;
        int gr = r0 + row;
        float4 v = (gr < M) ? *(const float4*)(A + (size_t)gr * 128 + c4 * 4)
                            : make_float4(0.f, 0.f, 0.f, 0.f);
        *(float4*)(&xs[row][c4 * 4]) = v;
    }
    for (int i = tid; i < 2048; i += 256) ws[i >> 4][i & 15] = W[i];
    __syncthreads();

    int col = tid & 15;
    int rq  = tid >> 4;
    float acc[4] = {0.f, 0.f, 0.f, 0.f};
    for (int k = 0; k < 128; k++) {
        float w = ws[k][col];
#pragma unroll
        for (int r = 0; r < 4; r++)
            acc[r] = fmaf(xs[rq * 4 + r][k], w, acc[r]);
    }
#pragma unroll
    for (int r = 0; r < 4; r++) {
        int gr = r0 + rq * 4 + r;
        if (gr < M) C[(size_t)gr * 16 + col] = acc[r];
    }
}

// ---------------- aggregation, F=128 (MLP-8 predicated gather; fp16 or fp32 input) ----------------
template <bool RELU, bool IN_HALF>
__global__ __launch_bounds__(256) void agg128(
    const void* __restrict__ hv, const float* __restrict__ bias,
    float4* __restrict__ outF)
{
    int warp = (blockIdx.x * blockDim.x + threadIdx.x) >> 5;
    int lane = threadIdx.x & 31;
    if (warp >= NN) return;
    int v = warp;

    auto ldrow = [&](size_t row) -> float4 {
        if (IN_HALF) {
            uint2 u = ((const uint2*)hv)[row * 32 + lane];
            float2 fa = __half22float2(*(__half2*)&u.x);
            float2 fb = __half22float2(*(__half2*)&u.y);
            return make_float4(fa.x, fa.y, fb.x, fb.y);
        } else {
            return ((const float4*)hv)[row * 32 + lane];
        }
    };

    float dv = g_dinv[v];
    float4 self = ldrow((size_t)v);
    float4 acc;
    acc.x = dv * self.x; acc.y = dv * self.y;
    acc.z = dv * self.z; acc.w = dv * self.w;

    int rs = g_row[v], re = g_row[v + 1];
    for (int base = rs; base < re; base += 32) {
        int avail = re - base;
        int   s = 0;
        float d = 0.f;
        if (lane < avail) { s = g_csrc[base + lane]; d = g_dinv[s]; }
        int m = avail < 32 ? avail : 32;
        for (int j = 0; j < m; j += 8) {
            int   sj[8];
            float dj[8];
#pragma unroll
            for (int q = 0; q < 8; q++) {
                sj[q] = __shfl_sync(0xffffffffu, s, j + q);
                dj[q] = __shfl_sync(0xffffffffu, d, j + q);
            }
            float4 hvv[8];
#pragma unroll
            for (int q = 0; q < 8; q++)
                hvv[q] = ldrow((size_t)sj[q]);
#pragma unroll
            for (int q = 0; q < 8; q++) {
                acc.x = fmaf(dj[q], hvv[q].x, acc.x);
                acc.y = fmaf(dj[q], hvv[q].y, acc.y);
                acc.z = fmaf(dj[q], hvv[q].z, acc.z);
                acc.w = fmaf(dj[q], hvv[q].w, acc.w);
            }
        }
    }

    float4 bb = *(const float4*)(bias + 4 * lane);
    acc.x = fmaf(acc.x, dv, bb.x);
    acc.y = fmaf(acc.y, dv, bb.y);
    acc.z = fmaf(acc.z, dv, bb.z);
    acc.w = fmaf(acc.w, dv, bb.w);
    if (RELU) {
        acc.x = fmaxf(acc.x, 0.f); acc.y = fmaxf(acc.y, 0.f);
        acc.z = fmaxf(acc.z, 0.f); acc.w = fmaxf(acc.w, 0.f);
    }
    outF[(size_t)v * 32 + lane] = acc;
}

// ---------------- aggregation, F=16 (MLP-8 predicated gather) ----------------
__global__ __launch_bounds__(256) void agg16(
    const float* __restrict__ h, const float* __restrict__ bias,
    float* __restrict__ out)
{
    int warp = (blockIdx.x * blockDim.x + threadIdx.x) >> 5;
    int lane = threadIdx.x & 31;
    if (warp >= NN) return;
    int v = warp;

    float dv = g_dinv[v];
    float acc = (lane < 16) ? dv * h[(size_t)v * 16 + lane] : 0.f;

    int rs = g_row[v], re = g_row[v + 1];
    for (int base = rs; base < re; base += 32) {
        int avail = re - base;
        int   s = 0;
        float d = 0.f;
        if (lane < avail) { s = g_csrc[base + lane]; d = g_dinv[s]; }
        int m = avail < 32 ? avail : 32;
        for (int j = 0; j < m; j += 8) {
            int   sj[8];
            float dj[8];
#pragma unroll
            for (int q = 0; q < 8; q++) {
                sj[q] = __shfl_sync(0xffffffffu, s, j + q);
                dj[q] = __shfl_sync(0xffffffffu, d, j + q);
            }
            float hv[8];
#pragma unroll
            for (int q = 0; q < 8; q++)
                hv[q] = (lane < 16) ? h[(size_t)sj[q] * 16 + lane] : 0.f;
#pragma unroll
            for (int q = 0; q < 8; q++)
                acc = fmaf(dj[q], hv[q], acc);
        }
    }

    if (lane < 16) {
        acc = fmaf(acc, dv, bias[lane]);
        out[(size_t)v * 16 + lane] = acc;
    }
}

// ---------------- launch ----------------
extern "C" void kernel_launch(void* const* d_in, const int* in_sizes, int n_in,
                              void* d_out, int out_size)
{
    const float* x  = (const float*)d_in[0];
    const int*   ei = (const int*)d_in[1];
    const float* W1 = (const float*)d_in[2];
    const float* b1 = (const float*)d_in[3];
    const float* W2 = (const float*)d_in[4];
    const float* b2 = (const float*)d_in[5];
    const float* W3 = (const float*)d_in[6];
    const float* b3 = (const float*)d_in[7];
    float* out = (float*)d_out;

    float *pH, *pHB, *pC16;
    __half* pH16;
    __nv_bfloat16 *pW1P, *pW2P;
    cudaGetSymbolAddress((void**)&pH,   g_h);
    cudaGetSymbolAddress((void**)&pH16, g_h16);
    cudaGetSymbolAddress((void**)&pHB,  g_hb);
    cudaGetSymbolAddress((void**)&pC16, g_c16);
    cudaGetSymbolAddress((void**)&pW1P, g_w1p);
    cudaGetSymbolAddress((void**)&pW2P, g_w2p);

    static cudaStream_t s1 = nullptr;
    static cudaEvent_t  e0 = nullptr, e1 = nullptr;
    if (!s1) {
        cudaStreamCreateWithFlags(&s1, cudaStreamNonBlocking);
        cudaEventCreateWithFlags(&e0, cudaEventDisableTiming);
        cudaEventCreateWithFlags(&e1, cudaEventDisableTiming);
    }

    const int* e_src = ei;
    const int* e_dst = ei + EE;

    const int AGG_BLOCKS  = (NN + 7) / 8;
    const int GEMM_BLOCKS = MPAD / 128;  // 782

    // Fork: CSR chain + W2 split on s1, concurrent with W1 split + fgemm1 on stream 0.
    cudaEventRecord(e0, 0);
    cudaStreamWaitEvent(s1, e0, 0);

    // submissions 1-2 (s1): zero, hist
    k_zero_counts<<<(NN + 255) / 256, 256, 0, s1>>>();
    k_hist<<<(EE / 4 + 255) / 256, 256, 0, s1>>>(e_dst);

    // submissions 3-4 (stream 0): W1 split + fgemm1 (profiled slot = 4th)
    k_split_w<<<(256 * 32 + 255) / 256, 256>>>(W1, pW1P, 256);
    fgemm_mma<256, true><<<GEMM_BLOCKS, 256>>>(x, pW1P, pH16, NN);

    // remainder of CSR chain + W2 split on s1
    k_scan_part<<<NBLK, 256, 0, s1>>>();
    k_scan_top<<<1, 512, 0, s1>>>();
    k_scan_write<<<NBLK, 256, 0, s1>>>();
    k_scatter<<<(EE / 4 + 255) / 256, 256, 0, s1>>>(e_src, e_dst);
    k_split_w<<<(128 * 32 + 255) / 256, 256, 0, s1>>>(W2, pW2P, 128);
    cudaEventRecord(e1, s1);

    cudaStreamWaitEvent(0, e1, 0);   // stream0 now has fgemm1 + CSR done

    // Layer 1 aggregation (fp16 gather -> fp32 out)
    agg128<true, true><<<AGG_BLOCKS, 256>>>(pH16, b1, (float4*)pHB);

    // Layer 2 GEMM (padded rows of g_hb are zero -> unguarded reads safe)
    fgemm_mma<128, false><<<GEMM_BLOCKS, 256>>>(pHB, pW2P, pH, MPAD);

    // Layer 2 aggregation (fp32 gather)
    agg128<true, false><<<AGG_BLOCKS, 256>>>(pH, b2, (float4*)pHB);

    // Layer 3
    gemm16<<<(NN + 63) / 64, 256>>>(pHB, W3, pC16, NN);
    agg16<<<AGG_BLOCKS, 256>>>(pC16, b3, out);
}

// round 14
// speedup vs baseline: 1.1313x; 1.0688x over previous
#include <cuda_runtime.h>
#include <cuda_bf16.h>
#include <cuda_fp16.h>
#include <cuda_pipeline.h>
#include <cstdint>

#define NN 100000
#define EE 1600000
#define MPAD 100096     // 782 * 128
#define NBLK 391        // ceil(NN/256)

// ---------------- scratch ----------------
__device__ int   g_counts[NN];
__device__ int   g_bsum[NBLK];
__device__ int   g_boff[NBLK];
__device__ int   g_row[NN + 1];
__device__ int   g_cursor[NN];
__device__ float g_dinv[NN];
__device__ int   g_csrc[EE];

__device__ __half g_h16[(size_t)MPAD * 128]; // fgemm out (fp16, agg gather input)
__device__ float g_hb[(size_t)MPAD * 128];   // agg out (next GEMM input); rows >= NN stay 0
__device__ float g_c16[(size_t)MPAD * 16];
__device__ __nv_bfloat16 g_w1p[512 * 128];   // [W1h ; W1l]
__device__ __nv_bfloat16 g_w2p[256 * 128];   // [W2h ; W2l]

// ---------------- helpers ----------------
__device__ __forceinline__ uint32_t smem_to_u32(const void* p) {
    uint32_t a;
    asm("{ .reg .u64 t; cvta.to.shared.u64 t, %1; cvt.u32.u64 %0, t; }" : "=r"(a) : "l"(p));
    return a;
}

__device__ __forceinline__ void split4(float4 v, uint2& hi, uint2& lo) {
    __align__(8) __nv_bfloat16 h[4], l[4];
    float f[4] = {v.x, v.y, v.z, v.w};
#pragma unroll
    for (int i = 0; i < 4; i++) {
        h[i] = __float2bfloat16_rn(f[i]);
        l[i] = __float2bfloat16_rn(f[i] - __bfloat162float(h[i]));
    }
    hi = *(uint2*)h;
    lo = *(uint2*)l;
}

__device__ __forceinline__ void split2(float2 v, uint32_t& h, uint32_t& l) {
    __nv_bfloat16 h0 = __float2bfloat16_rn(v.x), h1 = __float2bfloat16_rn(v.y);
    float r0 = v.x - __bfloat162float(h0), r1 = v.y - __bfloat162float(h1);
    __nv_bfloat16 l0 = __float2bfloat16_rn(r0), l1 = __float2bfloat16_rn(r1);
    h = ((uint32_t)__bfloat16_as_ushort(h1) << 16) | (uint32_t)__bfloat16_as_ushort(h0);
    l = ((uint32_t)__bfloat16_as_ushort(l1) << 16) | (uint32_t)__bfloat16_as_ushort(l0);
}

__device__ __forceinline__ void ldsm_x4_t(uint32_t& r0, uint32_t& r1, uint32_t& r2, uint32_t& r3,
                                          uint32_t addr) {
    asm volatile("ldmatrix.sync.aligned.m8n8.x4.trans.shared.b16 {%0,%1,%2,%3}, [%4];"
                 : "=r"(r0), "=r"(r1), "=r"(r2), "=r"(r3) : "r"(addr));
}

__device__ __forceinline__ void mma_16816(float* c, const uint32_t* a, const uint32_t* b) {
    asm volatile(
        "mma.sync.aligned.m16n8k16.row.col.f32.bf16.bf16.f32 "
        "{%0,%1,%2,%3}, {%4,%5,%6,%7}, {%8,%9}, {%0,%1,%2,%3};"
        : "+f"(c[0]), "+f"(c[1]), "+f"(c[2]), "+f"(c[3])
        : "r"(a[0]), "r"(a[1]), "r"(a[2]), "r"(a[3]), "r"(b[0]), "r"(b[1]));
}

// W[K,128] -> WP[2K,128] = [Wh ; Wl]
__global__ void k_split_w(const float* __restrict__ W, __nv_bfloat16* __restrict__ WP, int K) {
    int i = blockIdx.x * blockDim.x + threadIdx.x;
    if (i >= K * 32) return;
    int row = i >> 5, c4 = (i & 31) * 4;
    float4 v = ((const float4*)W)[i];
    uint2 h, l; split4(v, h, l);
    *(uint2*)(WP + (size_t)row * 128 + c4)       = h;
    *(uint2*)(WP + (size_t)(K + row) * 128 + c4) = l;
}

// ---------------- CSR build ----------------
__global__ void k_zero_counts() {
    int i = blockIdx.x * blockDim.x + threadIdx.x;
    if (i < NN) g_counts[i] = 0;
}

__global__ void k_hist(const int* __restrict__ dst) {
    int i = blockIdx.x * blockDim.x + threadIdx.x;
    if (i < EE / 4) {
        int4 d = ((const int4*)dst)[i];
        atomicAdd(&g_counts[d.x], 1);
        atomicAdd(&g_counts[d.y], 1);
        atomicAdd(&g_counts[d.z], 1);
        atomicAdd(&g_counts[d.w], 1);
    }
}

__global__ void k_scan_part() {
    __shared__ int sm[256];
    int i = blockIdx.x * 256 + threadIdx.x;
    sm[threadIdx.x] = (i < NN) ? g_counts[i] : 0;
    __syncthreads();
#pragma unroll
    for (int off = 128; off > 0; off >>= 1) {
        if (threadIdx.x < off) sm[threadIdx.x] += sm[threadIdx.x + off];
        __syncthreads();
    }
    if (threadIdx.x == 0) g_bsum[blockIdx.x] = sm[0];
}

__global__ void k_scan_top() {
    __shared__ int sm[512];
    int t = threadIdx.x;
    sm[t] = (t < NBLK) ? g_bsum[t] : 0;
    __syncthreads();
    for (int off = 1; off < 512; off <<= 1) {
        int v = (t >= off) ? sm[t - off] : 0;
        __syncthreads();
        sm[t] += v;
        __syncthreads();
    }
    if (t < NBLK) g_boff[t] = (t == 0) ? 0 : sm[t - 1];
}

__global__ void k_scan_write() {
    int b = blockIdx.x, t = threadIdx.x;
    int i = b * 256 + t;
    int c = (i < NN) ? g_counts[i] : 0;
    int lane = t & 31, w = t >> 5;
    int v = c;
#pragma unroll
    for (int off = 1; off < 32; off <<= 1) {
        int u = __shfl_up_sync(0xffffffffu, v, off);
        if (lane >= off) v += u;
    }
    __shared__ int wsum[8];
    if (lane == 31) wsum[w] = v;
    __syncthreads();
    if (w == 0) {
        int x = (lane < 8) ? wsum[lane] : 0;
#pragma unroll
        for (int off = 1; off < 8; off <<= 1) {
            int u = __shfl_up_sync(0xffffffffu, x, off);
            if (lane >= off) x += u;
        }
        if (lane < 8) wsum[lane] = x;
    }
    __syncthreads();
    int excl = v - c + ((w > 0) ? wsum[w - 1] : 0) + g_boff[b];
    if (i < NN) {
        g_row[i]    = excl;
        g_cursor[i] = excl;
        g_dinv[i]   = rsqrtf((float)(c + 1));
    }
    if (i == NN - 1) g_row[NN] = excl + c;
}

__global__ void k_scatter(const int* __restrict__ src, const int* __restrict__ dst) {
    int i = blockIdx.x * blockDim.x + threadIdx.x;
    if (i < EE / 4) {
        int4 s = ((const int4*)src)[i];
        int4 d = ((const int4*)dst)[i];
        int p;
        p = atomicAdd(&g_cursor[d.x], 1); g_csrc[p] = s.x;
        p = atomicAdd(&g_cursor[d.y], 1); g_csrc[p] = s.y;
        p = atomicAdd(&g_cursor[d.z], 1); g_csrc[p] = s.z;
        p = atomicAdd(&g_cursor[d.w], 1); g_csrc[p] = s.w;
    }
}

// ---------------- raw-mma fused-split GEMM (16x128 warp tile): C = A_fp32 * W ----------------
// OUT_HALF: write C as fp16 (for the fp16 gather path).
template <int K, bool OUT_HALF>
__global__ __launch_bounds__(256, 2) void fgemm_mma(
    const float* __restrict__ A, const __nv_bfloat16* __restrict__ WP,
    void* __restrict__ Cv, int M)
{
    constexpr int NCH  = K / 32;
    constexpr int LDBB = 272;
    constexpr int HALF = 32 * LDBB;
    constexpr int STAGE = 2 * HALF;

    __shared__ __align__(16) char sB[2 * STAGE];

    const int tid  = threadIdx.x;
    const int warp = tid >> 5;
    const int lane = tid & 31;
    const int m0   = warp * 16;
    const size_t rowBase = (size_t)blockIdx.x * 128;
    const uint32_t sbase = smem_to_u32(sB);

    auto issueB = [&](int ch) {
        int st = ch & 1, k0 = ch * 32;
#pragma unroll
        for (int rep = 0; rep < 4; rep++) {
            int idx  = tid + rep * 256;
            int half = idx >> 9;
            int r    = (idx >> 4) & 31;
            int c16  = idx & 15;
            __pipeline_memcpy_async(
                sB + st * STAGE + half * HALF + r * LDBB + c16 * 16,
                (const char*)WP + ((size_t)(half * K + k0 + r) * 256 + c16 * 16), 16);
        }
    };

    const int rlo  = lane >> 2;
    const int tcol = (lane & 3) * 2;
    float2 p0, p1, p2, p3;
    auto ldA = [&](int g) {
        int k = g * 16 + tcol;
        size_t ra = rowBase + m0 + rlo;
        size_t rb = ra + 8;
        p0 = (ra < (size_t)M) ? *(const float2*)&A[ra * K + k]     : make_float2(0.f, 0.f);
        p1 = (rb < (size_t)M) ? *(const float2*)&A[rb * K + k]     : make_float2(0.f, 0.f);
        p2 = (ra < (size_t)M) ? *(const float2*)&A[ra * K + k + 8] : make_float2(0.f, 0.f);
        p3 = (rb < (size_t)M) ? *(const float2*)&A[rb * K + k + 8] : make_float2(0.f, 0.f);
    };

    float c[16][4];
#pragma unroll
    for (int i = 0; i < 16; i++)
#pragma unroll
        for (int j = 0; j < 4; j++) c[i][j] = 0.f;

    issueB(0);
    __pipeline_commit();
    ldA(0);

    const int krow  = (lane & 7) + ((lane >> 3) & 1) * 8;
    const int nside = ((lane >> 4) & 1) * 8;

    for (int ch = 0; ch < NCH; ch++) {
        int st = ch & 1;
        __pipeline_wait_prior(0);
        __syncthreads();
        if (ch + 1 < NCH) { issueB(ch + 1); __pipeline_commit(); }

#pragma unroll
        for (int h16 = 0; h16 < 2; h16++) {
            uint32_t ah[4], al[4];
            split2(p0, ah[0], al[0]);
            split2(p1, ah[1], al[1]);
            split2(p2, ah[2], al[2]);
            split2(p3, ah[3], al[3]);
            int g = ch * 2 + h16;
            if (g + 1 < K / 16) ldA(g + 1);

            uint32_t bh_base = sbase + st * STAGE + (h16 * 16 + krow) * LDBB + nside * 2;
            uint32_t bl_base = bh_base + HALF;
#pragma unroll
            for (int grp = 0; grp < 8; grp++) {
                uint32_t h0, h1, h2, h3, l0, l1, l2, l3;
                ldsm_x4_t(h0, h1, h2, h3, bh_base + grp * 32);
                ldsm_x4_t(l0, l1, l2, l3, bl_base + grp * 32);
                uint32_t bA[2] = {h0, h1}, bB[2] = {h2, h3};
                uint32_t lA[2] = {l0, l1}, lB[2] = {l2, l3};
                mma_16816(c[grp * 2],     ah, bA);
                mma_16816(c[grp * 2],     al, bA);
                mma_16816(c[grp * 2],     ah, lA);
                mma_16816(c[grp * 2 + 1], ah, bB);
                mma_16816(c[grp * 2 + 1], al, bB);
                mma_16816(c[grp * 2 + 1], ah, lB);
            }
        }
    }

    size_t ra = rowBase + m0 + rlo;
    if (OUT_HALF) {
        __half2* Ch = (__half2*)Cv;
#pragma unroll
        for (int n8 = 0; n8 < 16; n8++) {
            int col = n8 * 8 + tcol;       // even
            Ch[(ra * 128 + col) >> 1]       = __floats2half2_rn(c[n8][0], c[n8][1]);
            Ch[((ra + 8) * 128 + col) >> 1] = __floats2half2_rn(c[n8][2], c[n8][3]);
        }
    } else {
        float* C = (float*)Cv;
#pragma unroll
        for (int n8 = 0; n8 < 16; n8++) {
            int col = n8 * 8 + tcol;
            *(float2*)&C[ra * 128 + col]       = make_float2(c[n8][0], c[n8][1]);
            *(float2*)&C[(ra + 8) * 128 + col] = make_float2(c[n8][2], c[n8][3]);
        }
    }
}

// ---------------- small GEMM: C[M,16] = A[M,128] * W[128,16] ----------------
__global__ __launch_bounds__(256) void gemm16(
    const float* __restrict__ A, const float* __restrict__ W,
    float* __restrict__ C, int M)
{
    __shared__ float xs[64][132];
    __shared__ float ws[128][16];

    int tid = threadIdx.x;
    int r0 = blockIdx.x * 64;

    for (int i = tid; i < 2048; i += 256) {
        int row = i >> 5;
        int c4 = i & 31;
        int gr = r0 + row;
        float4 v = (gr < M) ? *(const float4*)(A + (size_t)gr * 128 + c4 * 4)
                            : make_float4(0.f, 0.f, 0.f, 0.f);
        *(float4*)(&xs[row][c4 * 4]) = v;
    }
    for (int i = tid; i < 2048; i += 256) ws[i >> 4][i & 15] = W[i];
    __syncthreads();

    int col = tid & 15;
    int rq  = tid >> 4;
    float acc[4] = {0.f, 0.f, 0.f, 0.f};
    for (int k = 0; k < 128; k++) {
        float w = ws[k][col];
#pragma unroll
        for (int r = 0; r < 4; r++)
            acc[r] = fmaf(xs[rq * 4 + r][k], w, acc[r]);
    }
#pragma unroll
    for (int r = 0; r < 4; r++) {
        int gr = r0 + rq * 4 + r;
        if (gr < M) C[(size_t)gr * 16 + col] = acc[r];
    }
}

// ---------------- aggregation, F=128 (MLP-8 predicated gather; fp16 input) ----------------
template <bool RELU>
__global__ __launch_bounds__(256) void agg128h(
    const __half* __restrict__ hv, const float* __restrict__ bias,
    float4* __restrict__ outF)
{
    int warp = (blockIdx.x * blockDim.x + threadIdx.x) >> 5;
    int lane = threadIdx.x & 31;
    if (warp >= NN) return;
    int v = warp;

    auto ldrow = [&](size_t row) -> float4 {
        uint2 u = ((const uint2*)hv)[row * 32 + lane];
        float2 fa = __half22float2(*(__half2*)&u.x);
        float2 fb = __half22float2(*(__half2*)&u.y);
        return make_float4(fa.x, fa.y, fb.x, fb.y);
    };

    float dv = g_dinv[v];
    float4 self = ldrow((size_t)v);
    float4 acc;
    acc.x = dv * self.x; acc.y = dv * self.y;
    acc.z = dv * self.z; acc.w = dv * self.w;

    int rs = g_row[v], re = g_row[v + 1];
    for (int base = rs; base < re; base += 32) {
        int avail = re - base;
        int   s = 0;
        float d = 0.f;
        if (lane < avail) { s = g_csrc[base + lane]; d = g_dinv[s]; }
        int m = avail < 32 ? avail : 32;
        for (int j = 0; j < m; j += 8) {
            int   sj[8];
            float dj[8];
#pragma unroll
            for (int q = 0; q < 8; q++) {
                sj[q] = __shfl_sync(0xffffffffu, s, j + q);
                dj[q] = __shfl_sync(0xffffffffu, d, j + q);
            }
            float4 hvv[8];
#pragma unroll
            for (int q = 0; q < 8; q++)
                hvv[q] = ldrow((size_t)sj[q]);
#pragma unroll
            for (int q = 0; q < 8; q++) {
                acc.x = fmaf(dj[q], hvv[q].x, acc.x);
                acc.y = fmaf(dj[q], hvv[q].y, acc.y);
                acc.z = fmaf(dj[q], hvv[q].z, acc.z);
                acc.w = fmaf(dj[q], hvv[q].w, acc.w);
            }
        }
    }

    float4 bb = *(const float4*)(bias + 4 * lane);
    acc.x = fmaf(acc.x, dv, bb.x);
    acc.y = fmaf(acc.y, dv, bb.y);
    acc.z = fmaf(acc.z, dv, bb.z);
    acc.w = fmaf(acc.w, dv, bb.w);
    if (RELU) {
        acc.x = fmaxf(acc.x, 0.f); acc.y = fmaxf(acc.y, 0.f);
        acc.z = fmaxf(acc.z, 0.f); acc.w = fmaxf(acc.w, 0.f);
    }
    outF[(size_t)v * 32 + lane] = acc;
}

// ---------------- aggregation, F=16 (MLP-8 predicated gather) ----------------
__global__ __launch_bounds__(256) void agg16(
    const float* __restrict__ h, const float* __restrict__ bias,
    float* __restrict__ out)
{
    int warp = (blockIdx.x * blockDim.x + threadIdx.x) >> 5;
    int lane = threadIdx.x & 31;
    if (warp >= NN) return;
    int v = warp;

    float dv = g_dinv[v];
    float acc = (lane < 16) ? dv * h[(size_t)v * 16 + lane] : 0.f;

    int rs = g_row[v], re = g_row[v + 1];
    for (int base = rs; base < re; base += 32) {
        int avail = re - base;
        int   s = 0;
        float d = 0.f;
        if (lane < avail) { s = g_csrc[base + lane]; d = g_dinv[s]; }
        int m = avail < 32 ? avail : 32;
        for (int j = 0; j < m; j += 8) {
            int   sj[8];
            float dj[8];
#pragma unroll
            for (int q = 0; q < 8; q++) {
                sj[q] = __shfl_sync(0xffffffffu, s, j + q);
                dj[q] = __shfl_sync(0xffffffffu, d, j + q);
            }
            float hv[8];
#pragma unroll
            for (int q = 0; q < 8; q++)
                hv[q] = (lane < 16) ? h[(size_t)sj[q] * 16 + lane] : 0.f;
#pragma unroll
            for (int q = 0; q < 8; q++)
                acc = fmaf(dj[q], hv[q], acc);
        }
    }

    if (lane < 16) {
        acc = fmaf(acc, dv, bias[lane]);
        out[(size_t)v * 16 + lane] = acc;
    }
}

// ---------------- launch ----------------
extern "C" void kernel_launch(void* const* d_in, const int* in_sizes, int n_in,
                              void* d_out, int out_size)
{
    const float* x  = (const float*)d_in[0];
    const int*   ei = (const int*)d_in[1];
    const float* W1 = (const float*)d_in[2];
    const float* b1 = (const float*)d_in[3];
    const float* W2 = (const float*)d_in[4];
    const float* b2 = (const float*)d_in[5];
    const float* W3 = (const float*)d_in[6];
    const float* b3 = (const float*)d_in[7];
    float* out = (float*)d_out;

    float *pHB, *pC16;
    __half* pH16;
    __nv_bfloat16 *pW1P, *pW2P;
    cudaGetSymbolAddress((void**)&pH16, g_h16);
    cudaGetSymbolAddress((void**)&pHB,  g_hb);
    cudaGetSymbolAddress((void**)&pC16, g_c16);
    cudaGetSymbolAddress((void**)&pW1P, g_w1p);
    cudaGetSymbolAddress((void**)&pW2P, g_w2p);

    static cudaStream_t s1 = nullptr;
    static cudaEvent_t  e0 = nullptr, e1 = nullptr;
    if (!s1) {
        cudaStreamCreateWithFlags(&s1, cudaStreamNonBlocking);
        cudaEventCreateWithFlags(&e0, cudaEventDisableTiming);
        cudaEventCreateWithFlags(&e1, cudaEventDisableTiming);
    }

    const int* e_src = ei;
    const int* e_dst = ei + EE;

    const int AGG_BLOCKS  = (NN + 7) / 8;
    const int GEMM_BLOCKS = MPAD / 128;  // 782

    // Fork: CSR chain + W2 split on s1, concurrent with W1 split + fgemm1 on stream 0.
    cudaEventRecord(e0, 0);
    cudaStreamWaitEvent(s1, e0, 0);

    // submissions 1-2 (s1): zero, hist
    k_zero_counts<<<(NN + 255) / 256, 256, 0, s1>>>();
    k_hist<<<(EE / 4 + 255) / 256, 256, 0, s1>>>(e_dst);

    // submissions 3-4 (stream 0): W1 split + fgemm1 (profiled slot = 4th)
    k_split_w<<<(256 * 32 + 255) / 256, 256>>>(W1, pW1P, 256);
    fgemm_mma<256, true><<<GEMM_BLOCKS, 256>>>(x, pW1P, pH16, NN);

    // remainder of CSR chain + W2 split on s1
    k_scan_part<<<NBLK, 256, 0, s1>>>();
    k_scan_top<<<1, 512, 0, s1>>>();
    k_scan_write<<<NBLK, 256, 0, s1>>>();
    k_scatter<<<(EE / 4 + 255) / 256, 256, 0, s1>>>(e_src, e_dst);
    k_split_w<<<(128 * 32 + 255) / 256, 256, 0, s1>>>(W2, pW2P, 128);
    cudaEventRecord(e1, s1);

    cudaStreamWaitEvent(0, e1, 0);   // stream0 now has fgemm1 + CSR done

    // Layer 1 aggregation (fp16 gather -> fp32 out)
    agg128h<true><<<AGG_BLOCKS, 256>>>(pH16, b1, (float4*)pHB);

    // Layer 2 GEMM (padded rows of g_hb are zero -> unguarded reads safe); fp16 out
    fgemm_mma<128, true><<<GEMM_BLOCKS, 256>>>(pHB, pW2P, pH16, MPAD);

    // Layer 2 aggregation (fp16 gather -> fp32 out)
    agg128h<true><<<AGG_BLOCKS, 256>>>(pH16, b2, (float4*)pHB);

    // Layer 3
    gemm16<<<(NN + 63) / 64, 256>>>(pHB, W3, pC16, NN);
    agg16<<<AGG_BLOCKS, 256>>>(pC16, b3, out);
}